// round 1
// baseline (speedup 1.0000x reference)
#include <cuda_runtime.h>
#include <cuda_bf16.h>

#define H 1024
#define V 32000
#define L 64
#define E 3
#define EOS_TOK 1

// ---------------- device scratch (no allocations allowed) ----------------
__device__ __align__(16) float g_X[E * L * H];        // gathered encoder inputs
__device__ float g_gi[E * L * 3 * H];                 // precomputed W_ih @ x + b_ih
__device__ __align__(16) float g_h[2][E * H];         // encoder hidden, double-buffered
__device__ float g_outs[E * L * H];                   // per-encoder outputs
__device__ float g_encouts[L * H];                    // combined encoder outputs
__device__ __align__(16) float g_dech[H];             // decoder hidden
__device__ __align__(16) float g_h2[H];               // candidate next hidden
__device__ float g_awraw[L];                          // raw attention logits
__device__ __align__(16) float g_applied[H];          // attention-applied context
__device__ __align__(16) float g_xvec[H];             // decoder GRU input
__device__ float g_raw[V];                            // raw output logits
__device__ unsigned long long g_blockmax[V / 8];      // packed (value,index) per block
__device__ float g_blocksum[V / 8];                   // partial sum of exp per block
__device__ int g_tok;
__device__ int g_done;
__device__ float g_logZ;

// ---------------- helpers ----------------
__device__ __forceinline__ float sigmoidf_(float x) { return 1.0f / (1.0f + expf(-x)); }

// warp-collective dot product; n multiple of 128; result valid on lane 0
__device__ __forceinline__ float warp_dot(const float* __restrict__ a,
                                          const float* __restrict__ b, int n) {
    int lane = threadIdx.x & 31;
    const float4* a4 = (const float4*)a;
    const float4* b4 = (const float4*)b;
    int n4 = n >> 2;
    float s = 0.0f;
    #pragma unroll 4
    for (int i = lane; i < n4; i += 32) {
        float4 x = a4[i], y = b4[i];
        s += x.x * y.x + x.y * y.y + x.z * y.z + x.w * y.w;
    }
    #pragma unroll
    for (int o = 16; o; o >>= 1) s += __shfl_down_sync(0xffffffffu, s, o);
    return s;
}

__device__ __forceinline__ unsigned f2mono(float x) {
    unsigned u = __float_as_uint(x);
    return (u & 0x80000000u) ? ~u : (u | 0x80000000u);
}

// ---------------- init ----------------
__global__ void k_init() {
    int i = threadIdx.x;
    for (int j = i; j < E * H; j += 1024) g_h[0][j] = 0.0f;
    if (i < H) g_dech[i] = 0.0f;
    if (i == 0) { g_tok = 0; g_done = 0; }
}

// ---------------- encoder: gather embeddings ----------------
__global__ void k_gather(const int* __restrict__ qids, const int* __restrict__ cids,
                         const float* __restrict__ emb) {
    int e = blockIdx.x / L, t = blockIdx.x % L;
    int id = (e == 0) ? qids[t] : cids[(e - 1) * L + t];
    const float* src = emb + ((long long)e * V + id) * H;
    float* dst = g_X + (e * L + t) * H;
    for (int j = threadIdx.x; j < H; j += blockDim.x) dst[j] = src[j];
}

// ---------------- encoder: gi = W_ih @ X + b_ih for all steps (tiled GEMM) ----
__global__ void k_gi(const float* __restrict__ W, const float* __restrict__ b) {
    __shared__ float Ws[16][65];
    __shared__ float Xs[64][65];
    int e = blockIdx.x / 192, rb = blockIdx.x % 192;
    int row0 = rb * 16;
    const float* Wb = W + ((long long)e * 3 * H + row0) * H;
    const float* Xb = g_X + e * L * H;
    float acc[4] = {0.f, 0.f, 0.f, 0.f};
    int r = threadIdx.x & 15;
    int tb = threadIdx.x >> 4;   // 0..15
    for (int kt = 0; kt < 16; kt++) {
        for (int i = threadIdx.x; i < 16 * 64; i += 256)
            Ws[i >> 6][i & 63] = Wb[(long long)(i >> 6) * H + kt * 64 + (i & 63)];
        for (int i = threadIdx.x; i < 64 * 64; i += 256)
            Xs[i >> 6][i & 63] = Xb[(i >> 6) * H + kt * 64 + (i & 63)];
        __syncthreads();
        #pragma unroll
        for (int k = 0; k < 64; k++) {
            float w = Ws[r][k];
            acc[0] += w * Xs[tb][k];
            acc[1] += w * Xs[tb + 16][k];
            acc[2] += w * Xs[tb + 32][k];
            acc[3] += w * Xs[tb + 48][k];
        }
        __syncthreads();
    }
    float bias = b[e * 3 * H + row0 + r];
    #pragma unroll
    for (int i = 0; i < 4; i++) {
        int t = tb + i * 16;
        g_gi[(e * L + t) * 3 * H + row0 + r] = acc[i] + bias;
    }
}

// ---------------- encoder: one recurrent step (W_hh matvec + gates fused) ----
__global__ void k_enc_step(const float* __restrict__ W_hh, const float* __restrict__ b_hh, int t) {
    int e = blockIdx.x / 128;
    int hi = (blockIdx.x % 128) * 8 + (threadIdx.x >> 5);
    const float* hin = g_h[t & 1] + e * H;
    float* hout = g_h[(t + 1) & 1] + e * H;
    const float* W = W_hh + (long long)e * 3 * H * H;
    float d0 = warp_dot(W + (long long)hi * H, hin, H);
    float d1 = warp_dot(W + (long long)(H + hi) * H, hin, H);
    float d2 = warp_dot(W + (long long)(2 * H + hi) * H, hin, H);
    if ((threadIdx.x & 31) == 0) {
        const float* gi = g_gi + (e * L + t) * 3 * H;
        const float* bh = b_hh + e * 3 * H;
        float r = sigmoidf_(gi[hi] + d0 + bh[hi]);
        float z = sigmoidf_(gi[H + hi] + d1 + bh[H + hi]);
        float n = tanhf(gi[2 * H + hi] + r * (d2 + bh[2 * H + hi]));
        float hn = (1.0f - z) * n + z * hin[hi];
        hout[hi] = hn;
        g_outs[(e * L + t) * H + hi] = hn;
    }
}

// ---------------- encoder: ensemble combine ----------------
__global__ void k_combine() {
    int i = blockIdx.x * 256 + threadIdx.x;   // 64*1024 total
    g_encouts[i] = g_outs[i] + 0.5f * (g_outs[L * H + i] + g_outs[2 * L * H + i]);
}

// ---------------- decoder: attention logits ----------------
__global__ void k_attn(const float* __restrict__ dec_emb, const float* __restrict__ W_attn,
                       const float* __restrict__ b_attn) {
    int l = blockIdx.x * 8 + (threadIdx.x >> 5);   // 8 blocks x 8 warps = 64
    int tok = g_tok;
    const float* e = dec_emb + (long long)tok * H;
    const float* Wr = W_attn + l * 2 * H;
    float s = warp_dot(Wr, e, H);
    float s2 = warp_dot(Wr + H, g_dech, H);
    if ((threadIdx.x & 31) == 0) g_awraw[l] = s + s2 + b_attn[l];
}

// ---------------- decoder: softmax + applied context ----------------
__global__ void k_apply(float* __restrict__ attns_out, int t) {
    __shared__ float raw[L];
    __shared__ float aw[L];
    if (threadIdx.x < L) raw[threadIdx.x] = g_awraw[threadIdx.x];
    __syncthreads();
    float m = -3.0e38f;
    for (int l = 0; l < L; l++) m = fmaxf(m, raw[l]);
    float ss = 0.0f;
    for (int l = 0; l < L; l++) ss += expf(raw[l] - m);
    if (threadIdx.x < L) aw[threadIdx.x] = expf(raw[threadIdx.x] - m) / ss;
    __syncthreads();
    int j = blockIdx.x * 128 + threadIdx.x;
    float acc = 0.0f;
    #pragma unroll 8
    for (int l = 0; l < L; l++) acc += aw[l] * g_encouts[l * H + j];
    g_applied[j] = acc;
    if (blockIdx.x == 0 && threadIdx.x < L) attns_out[t * L + threadIdx.x] = aw[threadIdx.x];
}

// ---------------- decoder: combine projection + relu ----------------
__global__ void k_comb(const float* __restrict__ dec_emb, const float* __restrict__ W_comb,
                       const float* __restrict__ b_comb) {
    int j = blockIdx.x * 8 + (threadIdx.x >> 5);   // 128 blocks
    const float* e = dec_emb + (long long)g_tok * H;
    const float* Wr = W_comb + j * 2 * H;
    float s = warp_dot(Wr, e, H);
    float s2 = warp_dot(Wr + H, g_applied, H);
    if ((threadIdx.x & 31) == 0) g_xvec[j] = fmaxf(s + s2 + b_comb[j], 0.0f);
}

// ---------------- decoder: GRU step (both matvecs + gates fused) ----------
__global__ void k_dgru(const float* __restrict__ W_ih, const float* __restrict__ W_hh,
                       const float* __restrict__ b_ih, const float* __restrict__ b_hh) {
    int hi = blockIdx.x * 8 + (threadIdx.x >> 5);   // 128 blocks
    float gi0 = warp_dot(W_ih + (long long)hi * H, g_xvec, H);
    float gi1 = warp_dot(W_ih + (long long)(H + hi) * H, g_xvec, H);
    float gi2 = warp_dot(W_ih + (long long)(2 * H + hi) * H, g_xvec, H);
    float gh0 = warp_dot(W_hh + (long long)hi * H, g_dech, H);
    float gh1 = warp_dot(W_hh + (long long)(H + hi) * H, g_dech, H);
    float gh2 = warp_dot(W_hh + (long long)(2 * H + hi) * H, g_dech, H);
    if ((threadIdx.x & 31) == 0) {
        float r = sigmoidf_(gi0 + b_ih[hi] + gh0 + b_hh[hi]);
        float z = sigmoidf_(gi1 + b_ih[H + hi] + gh1 + b_hh[H + hi]);
        float n = tanhf(gi2 + b_ih[2 * H + hi] + r * (gh2 + b_hh[2 * H + hi]));
        g_h2[hi] = (1.0f - z) * n + z * g_dech[hi];
    }
}

// ---------------- decoder: output projection, per-block max+sumexp ------
__global__ void k_out(const float* __restrict__ W_out, const float* __restrict__ b_out) {
    int w = threadIdx.x >> 5;
    int v = blockIdx.x * 8 + w;   // 4000 blocks
    float d = warp_dot(W_out + (long long)v * H, g_h2, H);
    __shared__ float sexp[8];
    __shared__ unsigned long long smax[8];
    if ((threadIdx.x & 31) == 0) {
        float raw = d + b_out[v];
        g_raw[v] = raw;
        sexp[w] = expf(raw);
        smax[w] = (((unsigned long long)f2mono(raw)) << 32) | (unsigned)(0xFFFFFFFFu - (unsigned)v);
    }
    __syncthreads();
    if (threadIdx.x == 0) {
        float s = 0.0f;
        unsigned long long mx = 0ull;
        #pragma unroll
        for (int i = 0; i < 8; i++) { s += sexp[i]; if (smax[i] > mx) mx = smax[i]; }
        g_blocksum[blockIdx.x] = s;
        g_blockmax[blockIdx.x] = mx;
    }
}

// ---------------- decoder: final reduce + state update -------------------
__global__ void k_reduce(float* __restrict__ toks_out, int t) {
    __shared__ float ssum[1024];
    __shared__ unsigned long long smx[1024];
    const int NB = V / 8;   // 4000
    float s = 0.0f;
    unsigned long long mx = 0ull;
    for (int i = threadIdx.x; i < NB; i += 1024) {
        s += g_blocksum[i];
        unsigned long long q = g_blockmax[i];
        if (q > mx) mx = q;
    }
    ssum[threadIdx.x] = s;
    smx[threadIdx.x] = mx;
    __syncthreads();
    for (int o = 512; o; o >>= 1) {
        if (threadIdx.x < o) {
            ssum[threadIdx.x] += ssum[threadIdx.x + o];
            if (smx[threadIdx.x + o] > smx[threadIdx.x]) smx[threadIdx.x] = smx[threadIdx.x + o];
        }
        __syncthreads();
    }
    int done_prev = g_done;
    __syncthreads();   // all threads read g_done before thread 0 rewrites it
    if (threadIdx.x == 0) {
        g_logZ = logf(ssum[0]);
        int nxt = (int)(0xFFFFFFFFu - (unsigned)(smx[0] & 0xFFFFFFFFull));
        int tok_out = done_prev ? g_tok : nxt;
        toks_out[t] = (float)tok_out;
        if (!done_prev) g_tok = nxt;
        g_done = done_prev | (nxt == EOS_TOK);
    }
    if (!done_prev) g_dech[threadIdx.x] = g_h2[threadIdx.x];
}

// ---------------- decoder: write log-softmax row --------------------------
__global__ void k_write(float* __restrict__ logits_out, int t) {
    int v = blockIdx.x * 256 + threadIdx.x;   // 125 blocks
    logits_out[(long long)t * V + v] = g_raw[v] - g_logZ;
}

// ---------------- host launch ----------------
extern "C" void kernel_launch(void* const* d_in, const int* in_sizes, int n_in,
                              void* d_out, int out_size) {
    const int* qids      = (const int*)d_in[0];
    const int* cids      = (const int*)d_in[1];
    const float* enc_emb = (const float*)d_in[2];
    const float* enc_Wih = (const float*)d_in[3];
    const float* enc_Whh = (const float*)d_in[4];
    const float* enc_bih = (const float*)d_in[5];
    const float* enc_bhh = (const float*)d_in[6];
    const float* dec_emb = (const float*)d_in[7];
    const float* W_attn  = (const float*)d_in[8];
    const float* b_attn  = (const float*)d_in[9];
    const float* W_comb  = (const float*)d_in[10];
    const float* b_comb  = (const float*)d_in[11];
    const float* dW_ih   = (const float*)d_in[12];
    const float* dW_hh   = (const float*)d_in[13];
    const float* db_ih   = (const float*)d_in[14];
    const float* db_hh   = (const float*)d_in[15];
    const float* W_out   = (const float*)d_in[16];
    const float* b_out   = (const float*)d_in[17];

    float* out        = (float*)d_out;
    float* logits_out = out;
    float* attns_out  = out + (long long)L * V;
    float* toks_out   = attns_out + L * L;

    k_init<<<1, 1024>>>();
    k_gather<<<E * L, 256>>>(qids, cids, enc_emb);
    k_gi<<<E * 192, 256>>>(enc_Wih, enc_bih);
    for (int t = 0; t < L; t++)
        k_enc_step<<<E * 128, 256>>>(enc_Whh, enc_bhh, t);
    k_combine<<<L * H / 256, 256>>>();

    for (int t = 0; t < L; t++) {
        k_attn<<<8, 256>>>(dec_emb, W_attn, b_attn);
        k_apply<<<8, 128>>>(attns_out, t);
        k_comb<<<128, 256>>>(dec_emb, W_comb, b_comb);
        k_dgru<<<128, 256>>>(dW_ih, dW_hh, db_ih, db_hh);
        k_out<<<V / 8, 256>>>(W_out, b_out);
        k_reduce<<<1, 1024>>>(toks_out, t);
        k_write<<<V / 256, 256>>>(logits_out, t);
    }
}

// round 3
// speedup vs baseline: 1.2767x; 1.2767x over previous
#include <cuda_runtime.h>
#include <cuda_bf16.h>

#define H 1024
#define V 32000
#define L 64
#define E 3
#define EOS_TOK 1
#define NB2 2000   // k_out blocks (16 rows each)

// ---------------- device scratch (no allocations allowed) ----------------
__device__ __align__(16) float g_X[E * L * H];        // gathered encoder inputs
__device__ float g_gi[E * L * 3 * H];                 // precomputed W_ih @ x + b_ih
__device__ float g_outs[E * L * H];                   // per-encoder outputs (= hidden chain)
__device__ __align__(16) float g_zero[H];             // stays zero (module init)
__device__ float g_encouts[L * H];                    // combined encoder outputs
__device__ __align__(16) float g_dech[H];             // decoder hidden
__device__ __align__(16) float g_h2[H];               // candidate next hidden
__device__ float g_awraw[L];                          // raw attention logits
__device__ __align__(16) float g_applied[H];          // attention-applied context
__device__ __align__(16) float g_xvec[H];             // decoder GRU input
__device__ float g_raw[V];                            // raw output logits (bf16-weight path)
__device__ float g_blocksum2[NB2];                    // partial sum of exp per block
__device__ float g_blockcmax[NB2];                    // max raw per block
__device__ float g_blockabs[NB2];                     // max sum|w||h| per block
__device__ __align__(16) __nv_bfloat16 g_Wbf[(size_t)V * H];  // bf16 copy of W_out
__device__ int g_tok;
__device__ int g_done;
__device__ float g_logZ;

// ---------------- helpers ----------------
__device__ __forceinline__ float sigmoidf_(float x) { return 1.0f / (1.0f + expf(-x)); }

__device__ __forceinline__ float wred(float s) {
    #pragma unroll
    for (int o = 16; o; o >>= 1) s += __shfl_down_sync(0xffffffffu, s, o);
    return s;
}

// warp-collective dot product; n multiple of 128; result valid on lane 0
__device__ __forceinline__ float warp_dot(const float* __restrict__ a,
                                          const float* __restrict__ b, int n) {
    int lane = threadIdx.x & 31;
    const float4* a4 = (const float4*)a;
    const float4* b4 = (const float4*)b;
    int n4 = n >> 2;
    float s = 0.0f;
    #pragma unroll 8
    for (int i = lane; i < n4; i += 32) {
        float4 x = a4[i], y = b4[i];
        s += x.x * y.x + x.y * y.y + x.z * y.z + x.w * y.w;
    }
    return wred(s);
}

__device__ __forceinline__ unsigned f2mono(float x) {
    unsigned u = __float_as_uint(x);
    return (u & 0x80000000u) ? ~u : (u | 0x80000000u);
}

// ---------------- init ----------------
__global__ void k_init() {
    int i = threadIdx.x;
    if (i < H) g_dech[i] = 0.0f;
    if (i == 0) { g_tok = 0; g_done = 0; }
}

// ---------------- convert W_out to bf16 (once per launch) ----------------
__global__ void k_prep(const float* __restrict__ W) {
    size_t i8 = ((size_t)blockIdx.x * 256 + threadIdx.x) * 8;
    const float4* W4 = (const float4*)W;
    float4 a = W4[i8 >> 2], b = W4[(i8 >> 2) + 1];
    __nv_bfloat16 tmp[8];
    tmp[0] = __float2bfloat16_rn(a.x); tmp[1] = __float2bfloat16_rn(a.y);
    tmp[2] = __float2bfloat16_rn(a.z); tmp[3] = __float2bfloat16_rn(a.w);
    tmp[4] = __float2bfloat16_rn(b.x); tmp[5] = __float2bfloat16_rn(b.y);
    tmp[6] = __float2bfloat16_rn(b.z); tmp[7] = __float2bfloat16_rn(b.w);
    *(uint4*)(g_Wbf + i8) = *(uint4*)tmp;
}

// ---------------- encoder: gather embeddings ----------------
__global__ void k_gather(const int* __restrict__ qids, const int* __restrict__ cids,
                         const float* __restrict__ emb) {
    int e = blockIdx.x / L, t = blockIdx.x % L;
    int id = (e == 0) ? qids[t] : cids[(e - 1) * L + t];
    const float* src = emb + ((long long)e * V + id) * H;
    float* dst = g_X + (e * L + t) * H;
    for (int j = threadIdx.x; j < H; j += blockDim.x) dst[j] = src[j];
}

// ---------------- encoder: gi = W_ih @ X + b_ih for all steps (tiled GEMM) ----
__global__ void k_gi(const float* __restrict__ W, const float* __restrict__ b) {
    __shared__ float Ws[16][65];
    __shared__ float Xs[64][65];
    int e = blockIdx.x / 192, rb = blockIdx.x % 192;
    int row0 = rb * 16;
    const float* Wb = W + ((long long)e * 3 * H + row0) * H;
    const float* Xb = g_X + e * L * H;
    float acc[4] = {0.f, 0.f, 0.f, 0.f};
    int r = threadIdx.x & 15;
    int tb = threadIdx.x >> 4;   // 0..15
    for (int kt = 0; kt < 16; kt++) {
        for (int i = threadIdx.x; i < 16 * 64; i += 256)
            Ws[i >> 6][i & 63] = Wb[(long long)(i >> 6) * H + kt * 64 + (i & 63)];
        for (int i = threadIdx.x; i < 64 * 64; i += 256)
            Xs[i >> 6][i & 63] = Xb[(i >> 6) * H + kt * 64 + (i & 63)];
        __syncthreads();
        #pragma unroll
        for (int k = 0; k < 64; k++) {
            float w = Ws[r][k];
            acc[0] += w * Xs[tb][k];
            acc[1] += w * Xs[tb + 16][k];
            acc[2] += w * Xs[tb + 32][k];
            acc[3] += w * Xs[tb + 48][k];
        }
        __syncthreads();
    }
    float bias = b[e * 3 * H + row0 + r];
    #pragma unroll
    for (int i = 0; i < 4; i++) {
        int t = tb + i * 16;
        g_gi[(e * L + t) * 3 * H + row0 + r] = acc[i] + bias;
    }
}

// ---------------- encoder: one recurrent step (3 interleaved row-dots) ----
__global__ void k_enc_step(const float* __restrict__ W_hh, const float* __restrict__ b_hh, int t) {
    int e = blockIdx.x >> 7;
    int hi = ((blockIdx.x & 127) << 3) + (threadIdx.x >> 5);
    int lane = threadIdx.x & 31;
    const float* hin = (t == 0) ? g_zero : (g_outs + (e * L + t - 1) * H);
    const float4* h4 = (const float4*)hin;
    const float* W = W_hh + (long long)e * 3 * H * H;
    const float4* r0 = (const float4*)(W + (long long)hi * H);
    const float4* r1 = (const float4*)(W + (long long)(H + hi) * H);
    const float4* r2 = (const float4*)(W + (long long)(2 * H + hi) * H);
    float a0 = 0.f, a1 = 0.f, a2 = 0.f;
    #pragma unroll
    for (int i = 0; i < 8; i++) {
        int j = i * 32 + lane;
        float4 hv = h4[j];
        float4 w0 = r0[j], w1 = r1[j], w2 = r2[j];
        a0 += w0.x * hv.x + w0.y * hv.y + w0.z * hv.z + w0.w * hv.w;
        a1 += w1.x * hv.x + w1.y * hv.y + w1.z * hv.z + w1.w * hv.w;
        a2 += w2.x * hv.x + w2.y * hv.y + w2.z * hv.z + w2.w * hv.w;
    }
    a0 = wred(a0); a1 = wred(a1); a2 = wred(a2);
    if (lane == 0) {
        const float* gi = g_gi + (e * L + t) * 3 * H;
        const float* bh = b_hh + e * 3 * H;
        float r = sigmoidf_(gi[hi] + a0 + bh[hi]);
        float z = sigmoidf_(gi[H + hi] + a1 + bh[H + hi]);
        float n = tanhf(gi[2 * H + hi] + r * (a2 + bh[2 * H + hi]));
        g_outs[(e * L + t) * H + hi] = (1.0f - z) * n + z * hin[hi];
    }
}

// ---------------- encoder: ensemble combine ----------------
__global__ void k_combine() {
    int i = blockIdx.x * 256 + threadIdx.x;   // 64*1024 total
    g_encouts[i] = g_outs[i] + 0.5f * (g_outs[L * H + i] + g_outs[2 * L * H + i]);
}

// ---------------- decoder: attention logits ----------------
__global__ void k_attn(const float* __restrict__ dec_emb, const float* __restrict__ W_attn,
                       const float* __restrict__ b_attn) {
    int l = blockIdx.x * 8 + (threadIdx.x >> 5);   // 8 blocks x 8 warps = 64
    int tok = g_tok;
    const float* e = dec_emb + (long long)tok * H;
    const float* Wr = W_attn + l * 2 * H;
    float s = warp_dot(Wr, e, H);
    float s2 = warp_dot(Wr + H, g_dech, H);
    if ((threadIdx.x & 31) == 0) g_awraw[l] = s + s2 + b_attn[l];
}

// ---------------- decoder: softmax + applied context ----------------
__global__ void k_apply(float* __restrict__ attns_out, int t) {
    __shared__ float raw[L];
    __shared__ float aw[L];
    if (threadIdx.x < L) raw[threadIdx.x] = g_awraw[threadIdx.x];
    __syncthreads();
    float m = -3.0e38f;
    for (int l = 0; l < L; l++) m = fmaxf(m, raw[l]);
    float ss = 0.0f;
    for (int l = 0; l < L; l++) ss += expf(raw[l] - m);
    if (threadIdx.x < L) aw[threadIdx.x] = expf(raw[threadIdx.x] - m) / ss;
    __syncthreads();
    int j = blockIdx.x * 128 + threadIdx.x;
    float acc = 0.0f;
    #pragma unroll 8
    for (int l = 0; l < L; l++) acc += aw[l] * g_encouts[l * H + j];
    g_applied[j] = acc;
    if (blockIdx.x == 0 && threadIdx.x < L) attns_out[t * L + threadIdx.x] = aw[threadIdx.x];
}

// ---------------- decoder: combine projection + relu ----------------
__global__ void k_comb(const float* __restrict__ dec_emb, const float* __restrict__ W_comb,
                       const float* __restrict__ b_comb) {
    int j = blockIdx.x * 8 + (threadIdx.x >> 5);   // 128 blocks
    const float* e = dec_emb + (long long)g_tok * H;
    const float* Wr = W_comb + j * 2 * H;
    float s = warp_dot(Wr, e, H);
    float s2 = warp_dot(Wr + H, g_applied, H);
    if ((threadIdx.x & 31) == 0) g_xvec[j] = fmaxf(s + s2 + b_comb[j], 0.0f);
}

// ---------------- decoder: GRU step (6 interleaved row-dots) --------------
__global__ void k_dgru(const float* __restrict__ W_ih, const float* __restrict__ W_hh,
                       const float* __restrict__ b_ih, const float* __restrict__ b_hh) {
    int hi = blockIdx.x * 8 + (threadIdx.x >> 5);   // 128 blocks
    int lane = threadIdx.x & 31;
    const float4* x4 = (const float4*)g_xvec;
    const float4* h4 = (const float4*)g_dech;
    const float4* i0 = (const float4*)(W_ih + (long long)hi * H);
    const float4* i1 = (const float4*)(W_ih + (long long)(H + hi) * H);
    const float4* i2 = (const float4*)(W_ih + (long long)(2 * H + hi) * H);
    const float4* q0 = (const float4*)(W_hh + (long long)hi * H);
    const float4* q1 = (const float4*)(W_hh + (long long)(H + hi) * H);
    const float4* q2 = (const float4*)(W_hh + (long long)(2 * H + hi) * H);
    float gi0 = 0.f, gi1 = 0.f, gi2 = 0.f, gh0 = 0.f, gh1 = 0.f, gh2 = 0.f;
    #pragma unroll
    for (int i = 0; i < 8; i++) {
        int j = i * 32 + lane;
        float4 xv = x4[j], hv = h4[j];
        float4 wa = i0[j], wb = i1[j], wc = i2[j];
        float4 wd = q0[j], we = q1[j], wf = q2[j];
        gi0 += wa.x * xv.x + wa.y * xv.y + wa.z * xv.z + wa.w * xv.w;
        gi1 += wb.x * xv.x + wb.y * xv.y + wb.z * xv.z + wb.w * xv.w;
        gi2 += wc.x * xv.x + wc.y * xv.y + wc.z * xv.z + wc.w * xv.w;
        gh0 += wd.x * hv.x + wd.y * hv.y + wd.z * hv.z + wd.w * hv.w;
        gh1 += we.x * hv.x + we.y * hv.y + we.z * hv.z + we.w * hv.w;
        gh2 += wf.x * hv.x + wf.y * hv.y + wf.z * hv.z + wf.w * hv.w;
    }
    gi0 = wred(gi0); gi1 = wred(gi1); gi2 = wred(gi2);
    gh0 = wred(gh0); gh1 = wred(gh1); gh2 = wred(gh2);
    if (lane == 0) {
        float r = sigmoidf_(gi0 + b_ih[hi] + gh0 + b_hh[hi]);
        float z = sigmoidf_(gi1 + b_ih[H + hi] + gh1 + b_hh[H + hi]);
        float n = tanhf(gi2 + b_ih[2 * H + hi] + r * (gh2 + b_hh[2 * H + hi]));
        g_h2[hi] = (1.0f - z) * n + z * g_dech[hi];
    }
}

// ---------------- decoder: bf16 output projection + per-block stats -------
__global__ void k_out(const float* __restrict__ b_out) {
    __shared__ __align__(16) float h4s[H];
    __shared__ float s_exp[16], s_raw[16], s_abs[16];
    int tid = threadIdx.x, lane = tid & 31, w = tid >> 5;
    ((float4*)h4s)[tid] = ((const float4*)g_h2)[tid];   // 256 x float4 = 1024
    __syncthreads();
    const float4* hs4 = (const float4*)h4s;
    #pragma unroll
    for (int k = 0; k < 2; k++) {
        int v = blockIdx.x * 16 + w * 2 + k;
        const uint4* Wr = (const uint4*)(g_Wbf + (size_t)v * H);   // 128 uint4/row
        float acc = 0.f, aa = 0.f;
        #pragma unroll
        for (int jj = 0; jj < 4; jj++) {
            int j = jj * 32 + lane;
            uint4 u = Wr[j];
            float4 ha = hs4[2 * j], hb = hs4[2 * j + 1];
            float2 p0 = __bfloat1622float2(*(const __nv_bfloat162*)&u.x);
            float2 p1 = __bfloat1622float2(*(const __nv_bfloat162*)&u.y);
            float2 p2 = __bfloat1622float2(*(const __nv_bfloat162*)&u.z);
            float2 p3 = __bfloat1622float2(*(const __nv_bfloat162*)&u.w);
            acc += p0.x * ha.x + p0.y * ha.y + p1.x * ha.z + p1.y * ha.w
                 + p2.x * hb.x + p2.y * hb.y + p3.x * hb.z + p3.y * hb.w;
            aa += fabsf(p0.x * ha.x) + fabsf(p0.y * ha.y) + fabsf(p1.x * ha.z) + fabsf(p1.y * ha.w)
                + fabsf(p2.x * hb.x) + fabsf(p2.y * hb.y) + fabsf(p3.x * hb.z) + fabsf(p3.y * hb.w);
        }
        acc = wred(acc); aa = wred(aa);
        if (lane == 0) {
            float raw = acc + b_out[v];
            g_raw[v] = raw;
            s_exp[w * 2 + k] = expf(raw);
            s_raw[w * 2 + k] = raw;
            s_abs[w * 2 + k] = aa;
        }
    }
    __syncthreads();
    if (tid == 0) {
        float se = 0.f, rm = -3.0e38f, ab = 0.f;
        #pragma unroll
        for (int i = 0; i < 16; i++) {
            se += s_exp[i]; rm = fmaxf(rm, s_raw[i]); ab = fmaxf(ab, s_abs[i]);
        }
        g_blocksum2[blockIdx.x] = se;
        g_blockcmax[blockIdx.x] = rm;
        g_blockabs[blockIdx.x] = ab;
    }
}

// ---------------- decoder: reduce + exact fp32 argmax rescore + update ----
__global__ void k_reduce(const float* __restrict__ W_out, const float* __restrict__ b_out,
                         float* __restrict__ toks_out, int t) {
    __shared__ float ssum[1024];
    __shared__ float sam[1024];
    __shared__ float scm[1024];
    __shared__ int s_cand[64];
    __shared__ unsigned long long s_cpk[64];
    __shared__ int s_cnt;
    int tid = threadIdx.x;
    int done_prev = g_done;            // all threads read before thread 0 rewrites
    float s = 0.f, am = 0.f, cm = -3.0e38f;
    for (int i = tid; i < NB2; i += 1024) {
        s += g_blocksum2[i];
        am = fmaxf(am, g_blockabs[i]);
        cm = fmaxf(cm, g_blockcmax[i]);
    }
    ssum[tid] = s; sam[tid] = am; scm[tid] = cm;
    if (tid == 0) s_cnt = 0;
    __syncthreads();
    for (int o = 512; o; o >>= 1) {
        if (tid < o) {
            ssum[tid] += ssum[tid + o];
            sam[tid] = fmaxf(sam[tid], sam[tid + o]);
            scm[tid] = fmaxf(scm[tid], scm[tid + o]);
        }
        __syncthreads();
    }
    // tau bounds |true_fp32_logit - bf16_logit|: bf16 rounding <= 2^-9 per weight
    float tau = sam[0] * (1.5f / 512.0f) + 1e-6f;
    float thr = scm[0] - 2.0f * tau;
    for (int i = tid; i < V; i += 1024) {
        if (g_raw[i] >= thr) {
            int p = atomicAdd(&s_cnt, 1);
            if (p < 64) s_cand[p] = i;
        }
    }
    __syncthreads();
    int nc = min(s_cnt, 64);
    int w = tid >> 5;
    for (int c = w; c < nc; c += 32) {
        int v = s_cand[c];
        float d = warp_dot(W_out + (size_t)v * H, g_h2, H);
        if ((tid & 31) == 0)
            s_cpk[c] = (((unsigned long long)f2mono(d + b_out[v])) << 32)
                     | (unsigned)(0xFFFFFFFFu - (unsigned)v);
    }
    __syncthreads();
    if (tid == 0) {
        unsigned long long best = 0ull;
        for (int c = 0; c < nc; c++) if (s_cpk[c] > best) best = s_cpk[c];
        int nxt = (int)(0xFFFFFFFFu - (unsigned)(best & 0xFFFFFFFFull));
        g_logZ = logf(ssum[0]);
        int tok_out = done_prev ? g_tok : nxt;
        toks_out[t] = (float)tok_out;
        if (!done_prev) g_tok = nxt;
        g_done = done_prev | (nxt == EOS_TOK);
    }
    if (!done_prev) g_dech[tid] = g_h2[tid];
}

// ---------------- decoder: write log-softmax row --------------------------
__global__ void k_write(float* __restrict__ logits_out, int t) {
    int v = blockIdx.x * 256 + threadIdx.x;   // 125 blocks
    logits_out[(long long)t * V + v] = g_raw[v] - g_logZ;
}

// ---------------- host launch ----------------
extern "C" void kernel_launch(void* const* d_in, const int* in_sizes, int n_in,
                              void* d_out, int out_size) {
    const int* qids      = (const int*)d_in[0];
    const int* cids      = (const int*)d_in[1];
    const float* enc_emb = (const float*)d_in[2];
    const float* enc_Wih = (const float*)d_in[3];
    const float* enc_Whh = (const float*)d_in[4];
    const float* enc_bih = (const float*)d_in[5];
    const float* enc_bhh = (const float*)d_in[6];
    const float* dec_emb = (const float*)d_in[7];
    const float* W_attn  = (const float*)d_in[8];
    const float* b_attn  = (const float*)d_in[9];
    const float* W_comb  = (const float*)d_in[10];
    const float* b_comb  = (const float*)d_in[11];
    const float* dW_ih   = (const float*)d_in[12];
    const float* dW_hh   = (const float*)d_in[13];
    const float* db_ih   = (const float*)d_in[14];
    const float* db_hh   = (const float*)d_in[15];
    const float* W_out   = (const float*)d_in[16];
    const float* b_out   = (const float*)d_in[17];

    float* out        = (float*)d_out;
    float* logits_out = out;
    float* attns_out  = out + (long long)L * V;
    float* toks_out   = attns_out + L * L;

    k_init<<<1, 1024>>>();
    k_prep<<<(V * H) / (8 * 256), 256>>>(W_out);   // 16000 blocks
    k_gather<<<E * L, 256>>>(qids, cids, enc_emb);
    k_gi<<<E * 192, 256>>>(enc_Wih, enc_bih);
    for (int t = 0; t < L; t++)
        k_enc_step<<<E * 128, 256>>>(enc_Whh, enc_bhh, t);
    k_combine<<<L * H / 256, 256>>>();

    for (int t = 0; t < L; t++) {
        k_attn<<<8, 256>>>(dec_emb, W_attn, b_attn);
        k_apply<<<8, 128>>>(attns_out, t);
        k_comb<<<128, 256>>>(dec_emb, W_comb, b_comb);
        k_dgru<<<128, 256>>>(dW_ih, dW_hh, db_ih, db_hh);
        k_out<<<NB2, 256>>>(b_out);
        k_reduce<<<1, 1024>>>(W_out, b_out, toks_out, t);
        k_write<<<V / 256, 256>>>(logits_out, t);
    }
}